// round 15
// baseline (speedup 1.0000x reference)
#include <cuda_runtime.h>
#include <cuda_bf16.h>
#include <math.h>
#include <stdint.h>

#define BATCH 4
#define SEQ   8192
#define CH    768
#define N2    4096
#define MODES 4097
#define NBLK  8
#define LAM   0.01f

#define FWD_SCALE 0.011048543456039806f   // 1/sqrt(8192)
#define INV_SCALE 0.022097086912079613f   // sqrt(8192)/4096

// padded smem indexing: 1 extra float2 per 32 -> kills 128B-stride conflicts
#define IX(i) ((i) + ((i) >> 5))
#define FFT_BUF 4224
#define FFT_SMEM (FFT_BUF * 8)            // 33792 bytes (single in-place buffer)

#define WFRAG_HALF 18432                  // bf16 elems per layer: 6*12*32*8
#define WFRAG_N    (2 * WFRAG_HALF)       // per block n

// ---------------- device scratch ----------------
__device__ __nv_bfloat16  g_xTb[BATCH * CH * SEQ];       // x transposed [b][c][s], bf16
__device__ __nv_bfloat162 g_X [BATCH * CH * MODES];      // spectrum (re,im) bf16x2
__device__ __nv_bfloat16  g_yT[BATCH * CH * SEQ];        // irfft out [b][c][s]
__device__ __nv_bfloat16  g_wfrag[NBLK * WFRAG_N];       // fragment-packed weights
__device__ float2 g_wfft[N2];     // exp(-2*pi*i*t/4096)
__device__ float2 g_wr  [MODES];  // (cos,sin)(2*pi*k/8192)

// ---------------- tables ----------------
__global__ void init_tables_kernel() {
    int i = blockIdx.x * blockDim.x + threadIdx.x;
    if (i < N2) {
        float s, c;
        sincospif((float)i * (1.0f / 2048.0f), &s, &c);
        g_wfft[i] = make_float2(c, -s);
    }
    if (i < MODES) {
        float s, c;
        sincospif((float)i * (1.0f / 4096.0f), &s, &c);
        g_wr[i] = make_float2(c, s);
    }
}

// ---------------- one-shot weight fragment packing ----------------
__global__ void __launch_bounds__(512) pack_w_kernel(const float* __restrict__ w1,
                                                     const float* __restrict__ w2) {
    int n = blockIdx.x;
    const float* g_w1r = w1 + n * 9216;
    const float* g_w1i = w1 + 73728 + n * 9216;
    const float* g_w2r = w2 + n * 9216;
    const float* g_w2i = w2 + 73728 + n * 9216;
    __nv_bfloat16* dst = g_wfrag + n * WFRAG_N;
    for (int i = threadIdx.x; i < 9216; i += 512) {
        int d = i / 96, kout = i % 96;
        int k  = d >> 4;
        int r  = d & 15;
        int half = r >> 3;
        int t2   = (r & 7) >> 1;
        int e    = r & 1;
        int nt = kout >> 3, gg = kout & 7;
        int base = (((k * 12 + nt) * 32 + gg * 4 + t2) << 3) + half * 2 + e;
        dst[base]                  = __float2bfloat16_rn(g_w1r[i]);
        dst[base + 4]              = __float2bfloat16_rn(g_w1i[i]);
        dst[WFRAG_HALF + base]     = __float2bfloat16_rn(g_w2r[i]);
        dst[WFRAG_HALF + base + 4] = __float2bfloat16_rn(g_w2i[i]);
    }
}

// -------- transpose x: [b,s,c] fp32 -> xTb [b,c,s] bf16 (paired stores) -----
__global__ void __launch_bounds__(256) transpose_x_kernel(const float* __restrict__ x) {
    __shared__ float t[64][33];
    int b  = blockIdx.z;
    int c0 = blockIdx.x * 32;
    int s0 = blockIdx.y * 64;
    int tx = threadIdx.x, ty = threadIdx.y;
    #pragma unroll
    for (int i = 0; i < 8; i++) {
        int s = s0 + ty + 8 * i;
        t[ty + 8 * i][tx] = x[((size_t)b * SEQ + s) * CH + c0 + tx];
    }
    __syncthreads();
    #pragma unroll
    for (int i = 0; i < 4; i++) {
        int cc = c0 + ty + 8 * i;
        __nv_bfloat162 v = __floats2bfloat162_rn(t[2 * tx][cc - c0], t[2 * tx + 1][cc - c0]);
        *(__nv_bfloat162*)(g_xTb + ((size_t)b * CH + cc) * SEQ + s0 + 2 * tx) = v;
    }
}

// ---------------- complex helpers ----------------
__device__ __forceinline__ float2 cadd(float2 a, float2 b) { return make_float2(a.x + b.x, a.y + b.y); }
__device__ __forceinline__ float2 csub(float2 a, float2 b) { return make_float2(a.x - b.x, a.y - b.y); }
__device__ __forceinline__ float2 cmul(float2 a, float2 b) {
    return make_float2(fmaf(a.x, b.x, -a.y * b.y), fmaf(a.x, b.y, a.y * b.x));
}

// forward DFT4 (e^{-i}), in place
__device__ __forceinline__ void dft4(float2& a0, float2& a1, float2& a2, float2& a3) {
    float2 t0 = cadd(a0, a2), t1 = csub(a0, a2);
    float2 t2 = cadd(a1, a3), t3 = csub(a1, a3);
    a0 = cadd(t0, t2);
    a2 = csub(t0, t2);
    a1 = make_float2(t1.x + t3.y, t1.y - t3.x);
    a3 = make_float2(t1.x - t3.y, t1.y + t3.x);
}

// 16-pt DFT in registers; output X[j] lands in v[4*(j&3) + (j>>2)]
__device__ __forceinline__ void dft16(float2 v[16]) {
    #pragma unroll
    for (int i = 0; i < 4; i++) dft4(v[i], v[i + 4], v[i + 8], v[i + 12]);
    const float C1 = 0.92387953251128674f, S1 = 0.38268343236508978f, R = 0.70710678118654752f;
    v[5]  = cmul(make_float2( C1, -S1), v[5]);
    v[6]  = cmul(make_float2(  R,  -R), v[6]);
    v[7]  = cmul(make_float2( S1, -C1), v[7]);
    v[9]  = cmul(make_float2(  R,  -R), v[9]);
    v[10] = make_float2(v[10].y, -v[10].x);
    v[11] = cmul(make_float2( -R,  -R), v[11]);
    v[13] = cmul(make_float2( S1, -C1), v[13]);
    v[14] = cmul(make_float2( -R,  -R), v[14]);
    v[15] = cmul(make_float2(-C1,  S1), v[15]);
    #pragma unroll
    for (int k1 = 0; k1 < 4; k1++) dft4(v[4 * k1], v[4 * k1 + 1], v[4 * k1 + 2], v[4 * k1 + 3]);
}

// Stages 1 and 2 of the 4096-pt radix-16 Stockham (stage 0 fused by callers).
__device__ __forceinline__ void fft4096_tail(float2* A) {
    int tid = threadIdx.x;
    float2 v[16];
    // ---- stage 1: ls=4, m=16 ----
    {
        int q = tid & 15, p = tid >> 4;
        #pragma unroll
        for (int j = 0; j < 16; j++)
            v[j] = A[IX(q + ((p + (j << 4)) << 4))];
        __syncthreads();
        dft16(v);
        int twb = p << 4;
        #pragma unroll
        for (int j = 0; j < 16; j++) {
            float2 y = v[4 * (j & 3) + (j >> 2)];
            if (j > 0) y = cmul(g_wfft[j * twb], y);
            A[IX(q + ((16 * p + j) << 4))] = y;
        }
        __syncthreads();
    }
    // ---- stage 2: ls=8, p=0 -> twiddle-free, per-thread disjoint ----
    {
        #pragma unroll
        for (int j = 0; j < 16; j++)
            v[j] = A[IX(tid + (j << 8))];
        dft16(v);
        #pragma unroll
        for (int j = 0; j < 16; j++)
            A[IX(tid + (j << 8))] = v[4 * (j & 3) + (j >> 2)];
        __syncthreads();
    }
}

// ---------------- forward rfft: xTb bf16 -> X planar bf16x2 -----------------
__global__ void __launch_bounds__(256, 4) fwd_fft_kernel() {
    extern __shared__ char smraw[];
    float2* A = (float2*)smraw;
    int row = blockIdx.x;
    int tid = threadIdx.x;
    const __nv_bfloat162* xr = (const __nv_bfloat162*)(g_xTb + (size_t)row * SEQ);

    float2 v[16];
    #pragma unroll
    for (int j = 0; j < 16; j++) {
        __nv_bfloat162 p = xr[tid + (j << 8)];
        v[j] = make_float2(__bfloat162float(p.x), __bfloat162float(p.y));
    }
    dft16(v);
    #pragma unroll
    for (int j = 0; j < 16; j++) {
        float2 y = v[4 * (j & 3) + (j >> 2)];
        if (j > 0) y = cmul(g_wfft[j * tid], y);
        A[IX(16 * tid + j)] = y;
    }
    __syncthreads();
    fft4096_tail(A);

    __nv_bfloat162* X = g_X + (size_t)row * MODES;
    for (int k = tid; k <= 4096; k += 256) {
        float2 Zk = A[IX(k & 4095)];
        float2 Zc = A[IX((4096 - k) & 4095)];
        float Ex = 0.5f * (Zk.x + Zc.x), Ey = 0.5f * (Zk.y - Zc.y);
        float Ox = 0.5f * (Zk.x - Zc.x), Oy = 0.5f * (Zk.y + Zc.y);
        float2 w = g_wr[k];
        float re = Ex + w.x * Oy - w.y * Ox;
        float im = Ey - w.x * Ox - w.y * Oy;
        X[k] = __floats2bfloat162_rn(FWD_SCALE * re, FWD_SCALE * im);
    }
}

// ============== tensor-core block-diagonal complex 2-layer MLP ==============
// CTA = (mode-tile of 256, block n, batch b). 512 threads; 16 warps.
// Warp = (mode-group of 32 modes, nt-half of 6): each weight fragment load
// feeds 8 HMMAs (2 M-tiles), halving weight smem traffic. mma order cr/ci/cr/ci
// keeps dependent pairs at distance 2.
#define MT    256
#define MLP_THREADS 512
#define XPAD  104
#define RS    52                             // XPAD/2 words
#define SW_OFF   0                           // 73728 B fragments
#define SXR_OFF  (2 * WFRAG_HALF * 2)        // 73728 B
#define SXI_OFF  (SXR_OFF + MT * XPAD * 2)   // +53248
#define SB_OFF   (SXI_OFF + MT * XPAD * 2)   // +53248
#define MLP_SMEM (SB_OFF + 4 * 96 * 4)       // +1536 = 181760 B

__device__ __forceinline__ void mma_bf16(float* c, const uint32_t* a, uint32_t b0, uint32_t b1) {
    asm volatile(
        "mma.sync.aligned.m16n8k16.row.col.f32.bf16.bf16.f32 "
        "{%0,%1,%2,%3}, {%4,%5,%6,%7}, {%8,%9}, {%0,%1,%2,%3};"
        : "+f"(c[0]), "+f"(c[1]), "+f"(c[2]), "+f"(c[3])
        : "r"(a[0]), "r"(a[1]), "r"(a[2]), "r"(a[3]), "r"(b0), "r"(b1));
}

__global__ void __launch_bounds__(MLP_THREADS) mlp_mma_kernel(const float* __restrict__ b1,
                                                              const float* __restrict__ b2) {
    extern __shared__ char sm[];
    __nv_bfloat16* s_wf = (__nv_bfloat16*)(sm + SW_OFF);
    __nv_bfloat16* s_xr = (__nv_bfloat16*)(sm + SXR_OFF);
    __nv_bfloat16* s_xi = (__nv_bfloat16*)(sm + SXI_OFF);
    float*         s_bv = (float*)(sm + SB_OFF);

    const int tid = threadIdx.x;
    const int n   = blockIdx.y;
    const int b   = blockIdx.z;
    const int m0  = blockIdx.x * MT;

    {
        const uint4* src = (const uint4*)(g_wfrag + (size_t)n * WFRAG_N);
        uint4* dst = (uint4*)s_wf;
        #pragma unroll
        for (int i = tid; i < WFRAG_N / 8; i += MLP_THREADS)
            dst[i] = src[i];
    }
    if (tid < 96) {
        s_bv[tid]       = b1[n * 96 + tid];
        s_bv[96 + tid]  = b1[768 + n * 96 + tid];
        s_bv[192 + tid] = b2[n * 96 + tid];
        s_bv[288 + tid] = b2[768 + n * 96 + tid];
    }

    size_t rowbase = ((size_t)b * CH + n * 96) * (size_t)MODES;
    for (int i = tid; i < 96 * MT; i += MLP_THREADS) {
        int d = i >> 8, mm = i & (MT - 1);
        int mode = m0 + mm;
        __nv_bfloat162 xv = (mode < MODES) ? g_X[rowbase + (size_t)d * MODES + mode]
                                           : __nv_bfloat162{__float2bfloat16_rn(0.f), __float2bfloat16_rn(0.f)};
        s_xr[mm * XPAD + d] = xv.x;
        s_xi[mm * XPAD + d] = xv.y;
    }
    __syncthreads();

    const int lane = tid & 31;
    const int warp = tid >> 5;           // 0..15
    const int g  = lane >> 2;
    const int t  = lane & 3;
    const int group = warp >> 1;         // mode group 0..7
    const int nth   = warp & 1;          // nt half 0..1
    const int mrow  = group * 32;        // 32 modes per group
    const int ntb   = nth * 6;           // nt base

    const uint4*    Wf = (const uint4*)s_wf;
    const uint32_t* Xr = (const uint32_t*)s_xr;
    const uint32_t* Xi = (const uint32_t*)s_xi;
    const uint32_t SGN = 0x80008000u;

    float cr[6][2][4], ci[6][2][4];

    // ---------- layer 1 ----------
    #pragma unroll
    for (int nt = 0; nt < 6; nt++) {
        int ntg = ntb + nt;
        float br0 = s_bv[ntg * 8 + 2 * t], br1 = s_bv[ntg * 8 + 2 * t + 1];
        float bi0 = s_bv[96 + ntg * 8 + 2 * t], bi1 = s_bv[96 + ntg * 8 + 2 * t + 1];
        #pragma unroll
        for (int m = 0; m < 2; m++) {
            cr[nt][m][0] = br0; cr[nt][m][1] = br1; cr[nt][m][2] = br0; cr[nt][m][3] = br1;
            ci[nt][m][0] = bi0; ci[nt][m][1] = bi1; ci[nt][m][2] = bi0; ci[nt][m][3] = bi1;
        }
    }
    #pragma unroll
    for (int k = 0; k < 6; k++) {
        int kw = k * 8 + t;
        uint32_t ar[2][4], ai[2][4];
        #pragma unroll
        for (int m = 0; m < 2; m++) {
            int r0 = (mrow + m * 16 + g) * RS, r1 = (mrow + m * 16 + g + 8) * RS;
            ar[m][0] = Xr[r0 + kw];     ar[m][1] = Xr[r1 + kw];
            ar[m][2] = Xr[r0 + kw + 4]; ar[m][3] = Xr[r1 + kw + 4];
            ai[m][0] = Xi[r0 + kw];     ai[m][1] = Xi[r1 + kw];
            ai[m][2] = Xi[r0 + kw + 4]; ai[m][3] = Xi[r1 + kw + 4];
        }
        #pragma unroll
        for (int nt = 0; nt < 6; nt++) {
            uint4 wv = Wf[(k * 12 + ntb + nt) * 32 + lane];
            #pragma unroll
            for (int m = 0; m < 2; m++) {
                uint32_t nai[4];
                #pragma unroll
                for (int j = 0; j < 4; j++) nai[j] = ai[m][j] ^ SGN;
                mma_bf16(cr[nt][m], ar[m], wv.x, wv.y);
                mma_bf16(ci[nt][m], ai[m], wv.x, wv.y);
                mma_bf16(cr[nt][m], nai,   wv.z, wv.w);
                mma_bf16(ci[nt][m], ar[m], wv.z, wv.w);
            }
        }
    }
    __syncthreads();   // all warps finish reading x tile before overwrite
    {
        uint32_t* Xrw = (uint32_t*)s_xr;
        uint32_t* Xiw = (uint32_t*)s_xi;
        #pragma unroll
        for (int nt = 0; nt < 6; nt++) {
            int cw = (ntb + nt) * 4 + t;
            #pragma unroll
            for (int m = 0; m < 2; m++) {
                int r0 = (mrow + m * 16 + g) * RS, r1 = (mrow + m * 16 + g + 8) * RS;
                __nv_bfloat162 hh;
                hh = __floats2bfloat162_rn(fmaxf(cr[nt][m][0], 0.0f), fmaxf(cr[nt][m][1], 0.0f));
                Xrw[r0 + cw] = *(uint32_t*)&hh;
                hh = __floats2bfloat162_rn(fmaxf(cr[nt][m][2], 0.0f), fmaxf(cr[nt][m][3], 0.0f));
                Xrw[r1 + cw] = *(uint32_t*)&hh;
                hh = __floats2bfloat162_rn(fmaxf(ci[nt][m][0], 0.0f), fmaxf(ci[nt][m][1], 0.0f));
                Xiw[r0 + cw] = *(uint32_t*)&hh;
                hh = __floats2bfloat162_rn(fmaxf(ci[nt][m][2], 0.0f), fmaxf(ci[nt][m][3], 0.0f));
                Xiw[r1 + cw] = *(uint32_t*)&hh;
            }
        }
    }
    __syncthreads();   // o1 tile complete before layer-2 reads

    // ---------- layer 2 ----------
    #pragma unroll
    for (int nt = 0; nt < 6; nt++) {
        int ntg = ntb + nt;
        float br0 = s_bv[192 + ntg * 8 + 2 * t], br1 = s_bv[192 + ntg * 8 + 2 * t + 1];
        float bi0 = s_bv[288 + ntg * 8 + 2 * t], bi1 = s_bv[288 + ntg * 8 + 2 * t + 1];
        #pragma unroll
        for (int m = 0; m < 2; m++) {
            cr[nt][m][0] = br0; cr[nt][m][1] = br1; cr[nt][m][2] = br0; cr[nt][m][3] = br1;
            ci[nt][m][0] = bi0; ci[nt][m][1] = bi1; ci[nt][m][2] = bi0; ci[nt][m][3] = bi1;
        }
    }
    #pragma unroll
    for (int k = 0; k < 6; k++) {
        int kw = k * 8 + t;
        uint32_t ar[2][4], ai[2][4];
        #pragma unroll
        for (int m = 0; m < 2; m++) {
            int r0 = (mrow + m * 16 + g) * RS, r1 = (mrow + m * 16 + g + 8) * RS;
            ar[m][0] = Xr[r0 + kw];     ar[m][1] = Xr[r1 + kw];
            ar[m][2] = Xr[r0 + kw + 4]; ar[m][3] = Xr[r1 + kw + 4];
            ai[m][0] = Xi[r0 + kw];     ai[m][1] = Xi[r1 + kw];
            ai[m][2] = Xi[r0 + kw + 4]; ai[m][3] = Xi[r1 + kw + 4];
        }
        #pragma unroll
        for (int nt = 0; nt < 6; nt++) {
            uint4 wv = Wf[(72 + k * 12 + ntb + nt) * 32 + lane];
            #pragma unroll
            for (int m = 0; m < 2; m++) {
                uint32_t nai[4];
                #pragma unroll
                for (int j = 0; j < 4; j++) nai[j] = ai[m][j] ^ SGN;
                mma_bf16(cr[nt][m], ar[m], wv.x, wv.y);
                mma_bf16(ci[nt][m], ai[m], wv.x, wv.y);
                mma_bf16(cr[nt][m], nai,   wv.z, wv.w);
                mma_bf16(ci[nt][m], ar[m], wv.z, wv.w);
            }
        }
    }

    // ---------- softshrink + store (bf16x2) ----------
    #pragma unroll
    for (int nt = 0; nt < 6; nt++) {
        int ntg = ntb + nt;
        #pragma unroll
        for (int m = 0; m < 2; m++) {
            int mode_lo = m0 + mrow + m * 16 + g;
            int mode_hi = mode_lo + 8;
            #pragma unroll
            for (int j = 0; j < 4; j++) {
                int col  = ntg * 8 + 2 * t + (j & 1);
                int mode = (j < 2) ? mode_lo : mode_hi;
                if (mode < MODES) {
                    size_t off = rowbase + (size_t)col * MODES + mode;
                    float vr = cr[nt][m][j];
                    float vi = ci[nt][m][j];
                    vr = copysignf(fmaxf(fabsf(vr) - LAM, 0.0f), vr);
                    vi = copysignf(fmaxf(fabsf(vi) - LAM, 0.0f), vi);
                    g_X[off] = __floats2bfloat162_rn(vr, vi);
                }
            }
        }
    }
}

// ---------------- inverse rfft: X planar bf16x2 -> yT bf16 ------------------
__global__ void __launch_bounds__(256, 4) inv_fft_kernel() {
    extern __shared__ char smraw[];
    float2* A = (float2*)smraw;
    int row = blockIdx.x;
    int tid = threadIdx.x;
    const __nv_bfloat162* X = g_X + (size_t)row * MODES;

    float2 v[16];
    #pragma unroll
    for (int j = 0; j < 16; j++) {
        int k = tid + (j << 8);
        __nv_bfloat162 xk = X[k];
        __nv_bfloat162 xc = X[4096 - k];
        float xkr = __bfloat162float(xk.x), xki = __bfloat162float(xk.y);
        float xcr = __bfloat162float(xc.x), xci = __bfloat162float(xc.y);
        if (k == 0) { xki = 0.0f; xci = 0.0f; }
        float Ex = 0.5f * (xkr + xcr), Ey = 0.5f * (xki - xci);
        float Gx = 0.5f * (xkr - xcr), Gy = 0.5f * (xki + xci);
        float2 w = g_wr[k];
        float WOx = w.x * Gx - w.y * Gy;
        float WOy = w.x * Gy + w.y * Gx;
        v[j] = make_float2(INV_SCALE * (Ex - WOy), -INV_SCALE * (Ey + WOx));
    }
    dft16(v);
    #pragma unroll
    for (int j = 0; j < 16; j++) {
        float2 y = v[4 * (j & 3) + (j >> 2)];
        if (j > 0) y = cmul(g_wfft[j * tid], y);
        A[IX(16 * tid + j)] = y;
    }
    __syncthreads();
    fft4096_tail(A);

    __nv_bfloat162* out = (__nv_bfloat162*)(g_yT + (size_t)row * SEQ);
    for (int j = tid; j < 4096; j += 256) {
        float2 r = A[IX(j)];
        out[j] = __floats2bfloat162_rn(r.x, -r.y);
    }
}

// ---------------- transpose + bias: out[b,s,c] = x[b,s,c] + yT[b,c,s] -------
__global__ void __launch_bounds__(256) final_kernel(const float* __restrict__ x,
                                                    float* __restrict__ out) {
    __shared__ float t[32][33];
    int b  = blockIdx.z;
    int c0 = blockIdx.x * 32;
    int s0 = blockIdx.y * 32;
    int tx = threadIdx.x, ty = threadIdx.y;
    #pragma unroll
    for (int i = 0; i < 4; i++) {
        int cc = c0 + ty + 8 * i;
        t[ty + 8 * i][tx] = __bfloat162float(g_yT[((size_t)b * CH + cc) * SEQ + s0 + tx]);
    }
    __syncthreads();
    #pragma unroll
    for (int i = 0; i < 4; i++) {
        int s = s0 + ty + 8 * i;
        size_t off = ((size_t)b * SEQ + s) * CH + c0 + tx;
        out[off] = x[off] + t[tx][ty + 8 * i];
    }
}

// ---------------- launcher ----------------
extern "C" void kernel_launch(void* const* d_in, const int* in_sizes, int n_in,
                              void* d_out, int out_size) {
    const float* x  = (const float*)d_in[0];
    const float* w1 = (const float*)d_in[1];
    const float* b1 = (const float*)d_in[2];
    const float* w2 = (const float*)d_in[3];
    const float* b2 = (const float*)d_in[4];
    float* out = (float*)d_out;

    cudaFuncSetAttribute(fwd_fft_kernel, cudaFuncAttributeMaxDynamicSharedMemorySize, FFT_SMEM);
    cudaFuncSetAttribute(inv_fft_kernel, cudaFuncAttributeMaxDynamicSharedMemorySize, FFT_SMEM);
    cudaFuncSetAttribute(mlp_mma_kernel, cudaFuncAttributeMaxDynamicSharedMemorySize, MLP_SMEM);

    init_tables_kernel<<<17, 256>>>();
    pack_w_kernel<<<NBLK, 512>>>(w1, w2);
    transpose_x_kernel<<<dim3(CH / 32, SEQ / 64, BATCH), dim3(32, 8)>>>(x);
    fwd_fft_kernel<<<BATCH * CH, 256, FFT_SMEM>>>();
    mlp_mma_kernel<<<dim3((MODES + MT - 1) / MT, NBLK, BATCH), MLP_THREADS, MLP_SMEM>>>(b1, b2);
    inv_fft_kernel<<<BATCH * CH, 256, FFT_SMEM>>>();
    final_kernel<<<dim3(CH / 32, SEQ / 32, BATCH), dim3(32, 8)>>>(x, out);
}

// round 16
// speedup vs baseline: 1.0882x; 1.0882x over previous
#include <cuda_runtime.h>
#include <cuda_bf16.h>
#include <math.h>
#include <stdint.h>

#define BATCH 4
#define SEQ   8192
#define CH    768
#define N2    4096
#define MODES 4097
#define NBLK  8
#define LAM   0.01f

#define FWD_SCALE 0.011048543456039806f   // 1/sqrt(8192)
#define INV_SCALE 0.022097086912079613f   // sqrt(8192)/4096

// padded smem indexing: 1 extra float2 per 32 -> kills 128B-stride conflicts
#define IX(i) ((i) + ((i) >> 5))
#define FFT_BUF 4224
#define FFT_SMEM (FFT_BUF * 8)            // 33792 bytes (single in-place buffer)

#define WFRAG_HALF 18432                  // bf16 elems per layer: 6*12*32*8
#define WFRAG_N    (2 * WFRAG_HALF)       // per block n

// ---------------- device scratch ----------------
__device__ __nv_bfloat16  g_xTb[BATCH * CH * SEQ];       // x transposed [b][c][s], bf16
__device__ __nv_bfloat162 g_X [BATCH * CH * MODES];      // spectrum (re,im) bf16x2
__device__ __nv_bfloat16  g_yT[BATCH * CH * SEQ];        // irfft out [b][c][s]
__device__ __nv_bfloat16  g_wfrag[NBLK * WFRAG_N];       // fragment-packed weights
__device__ float2 g_wfft[N2];     // exp(-2*pi*i*t/4096)
__device__ float2 g_wr  [MODES];  // (cos,sin)(2*pi*k/8192)

// ---------------- tables ----------------
__global__ void init_tables_kernel() {
    int i = blockIdx.x * blockDim.x + threadIdx.x;
    if (i < N2) {
        float s, c;
        sincospif((float)i * (1.0f / 2048.0f), &s, &c);
        g_wfft[i] = make_float2(c, -s);
    }
    if (i < MODES) {
        float s, c;
        sincospif((float)i * (1.0f / 4096.0f), &s, &c);
        g_wr[i] = make_float2(c, s);
    }
}

// ---------------- one-shot weight fragment packing ----------------
__global__ void __launch_bounds__(512) pack_w_kernel(const float* __restrict__ w1,
                                                     const float* __restrict__ w2) {
    int n = blockIdx.x;
    const float* g_w1r = w1 + n * 9216;
    const float* g_w1i = w1 + 73728 + n * 9216;
    const float* g_w2r = w2 + n * 9216;
    const float* g_w2i = w2 + 73728 + n * 9216;
    __nv_bfloat16* dst = g_wfrag + n * WFRAG_N;
    for (int i = threadIdx.x; i < 9216; i += 512) {
        int d = i / 96, kout = i % 96;
        int k  = d >> 4;
        int r  = d & 15;
        int half = r >> 3;
        int t2   = (r & 7) >> 1;
        int e    = r & 1;
        int nt = kout >> 3, gg = kout & 7;
        int base = (((k * 12 + nt) * 32 + gg * 4 + t2) << 3) + half * 2 + e;
        dst[base]                  = __float2bfloat16_rn(g_w1r[i]);
        dst[base + 4]              = __float2bfloat16_rn(g_w1i[i]);
        dst[WFRAG_HALF + base]     = __float2bfloat16_rn(g_w2r[i]);
        dst[WFRAG_HALF + base + 4] = __float2bfloat16_rn(g_w2i[i]);
    }
}

// -------- transpose x: [b,s,c] fp32 -> xTb [b,c,s] bf16 (paired stores) -----
__global__ void __launch_bounds__(256) transpose_x_kernel(const float* __restrict__ x) {
    __shared__ float t[64][33];
    int b  = blockIdx.z;
    int c0 = blockIdx.x * 32;
    int s0 = blockIdx.y * 64;
    int tx = threadIdx.x, ty = threadIdx.y;
    #pragma unroll
    for (int i = 0; i < 8; i++) {
        int s = s0 + ty + 8 * i;
        t[ty + 8 * i][tx] = x[((size_t)b * SEQ + s) * CH + c0 + tx];
    }
    __syncthreads();
    #pragma unroll
    for (int i = 0; i < 4; i++) {
        int cc = c0 + ty + 8 * i;
        __nv_bfloat162 v = __floats2bfloat162_rn(t[2 * tx][cc - c0], t[2 * tx + 1][cc - c0]);
        *(__nv_bfloat162*)(g_xTb + ((size_t)b * CH + cc) * SEQ + s0 + 2 * tx) = v;
    }
}

// ---------------- complex helpers ----------------
__device__ __forceinline__ float2 cadd(float2 a, float2 b) { return make_float2(a.x + b.x, a.y + b.y); }
__device__ __forceinline__ float2 csub(float2 a, float2 b) { return make_float2(a.x - b.x, a.y - b.y); }
__device__ __forceinline__ float2 cmul(float2 a, float2 b) {
    return make_float2(fmaf(a.x, b.x, -a.y * b.y), fmaf(a.x, b.y, a.y * b.x));
}

// forward DFT4 (e^{-i}), in place
__device__ __forceinline__ void dft4(float2& a0, float2& a1, float2& a2, float2& a3) {
    float2 t0 = cadd(a0, a2), t1 = csub(a0, a2);
    float2 t2 = cadd(a1, a3), t3 = csub(a1, a3);
    a0 = cadd(t0, t2);
    a2 = csub(t0, t2);
    a1 = make_float2(t1.x + t3.y, t1.y - t3.x);
    a3 = make_float2(t1.x - t3.y, t1.y + t3.x);
}

// 16-pt DFT in registers; output X[j] lands in v[4*(j&3) + (j>>2)]
__device__ __forceinline__ void dft16(float2 v[16]) {
    #pragma unroll
    for (int i = 0; i < 4; i++) dft4(v[i], v[i + 4], v[i + 8], v[i + 12]);
    const float C1 = 0.92387953251128674f, S1 = 0.38268343236508978f, R = 0.70710678118654752f;
    v[5]  = cmul(make_float2( C1, -S1), v[5]);
    v[6]  = cmul(make_float2(  R,  -R), v[6]);
    v[7]  = cmul(make_float2( S1, -C1), v[7]);
    v[9]  = cmul(make_float2(  R,  -R), v[9]);
    v[10] = make_float2(v[10].y, -v[10].x);
    v[11] = cmul(make_float2( -R,  -R), v[11]);
    v[13] = cmul(make_float2( S1, -C1), v[13]);
    v[14] = cmul(make_float2( -R,  -R), v[14]);
    v[15] = cmul(make_float2(-C1,  S1), v[15]);
    #pragma unroll
    for (int k1 = 0; k1 < 4; k1++) dft4(v[4 * k1], v[4 * k1 + 1], v[4 * k1 + 2], v[4 * k1 + 3]);
}

// Stages 1 and 2 of the 4096-pt radix-16 Stockham (stage 0 fused by callers).
__device__ __forceinline__ void fft4096_tail(float2* A) {
    int tid = threadIdx.x;
    float2 v[16];
    // ---- stage 1: ls=4, m=16 ----
    {
        int q = tid & 15, p = tid >> 4;
        #pragma unroll
        for (int j = 0; j < 16; j++)
            v[j] = A[IX(q + ((p + (j << 4)) << 4))];
        __syncthreads();
        dft16(v);
        int twb = p << 4;
        #pragma unroll
        for (int j = 0; j < 16; j++) {
            float2 y = v[4 * (j & 3) + (j >> 2)];
            if (j > 0) y = cmul(g_wfft[j * twb], y);
            A[IX(q + ((16 * p + j) << 4))] = y;
        }
        __syncthreads();
    }
    // ---- stage 2: ls=8, p=0 -> twiddle-free, per-thread disjoint ----
    {
        #pragma unroll
        for (int j = 0; j < 16; j++)
            v[j] = A[IX(tid + (j << 8))];
        dft16(v);
        #pragma unroll
        for (int j = 0; j < 16; j++)
            A[IX(tid + (j << 8))] = v[4 * (j & 3) + (j >> 2)];
        __syncthreads();
    }
}

// ---------------- forward rfft: xTb bf16 -> X planar bf16x2 -----------------
__global__ void __launch_bounds__(256, 4) fwd_fft_kernel() {
    extern __shared__ char smraw[];
    float2* A = (float2*)smraw;
    int row = blockIdx.x;
    int tid = threadIdx.x;
    const __nv_bfloat162* xr = (const __nv_bfloat162*)(g_xTb + (size_t)row * SEQ);

    float2 v[16];
    #pragma unroll
    for (int j = 0; j < 16; j++) {
        __nv_bfloat162 p = xr[tid + (j << 8)];
        v[j] = make_float2(__bfloat162float(p.x), __bfloat162float(p.y));
    }
    dft16(v);
    #pragma unroll
    for (int j = 0; j < 16; j++) {
        float2 y = v[4 * (j & 3) + (j >> 2)];
        if (j > 0) y = cmul(g_wfft[j * tid], y);
        A[IX(16 * tid + j)] = y;
    }
    __syncthreads();
    fft4096_tail(A);

    __nv_bfloat162* X = g_X + (size_t)row * MODES;
    for (int k = tid; k <= 4096; k += 256) {
        float2 Zk = A[IX(k & 4095)];
        float2 Zc = A[IX((4096 - k) & 4095)];
        float Ex = 0.5f * (Zk.x + Zc.x), Ey = 0.5f * (Zk.y - Zc.y);
        float Ox = 0.5f * (Zk.x - Zc.x), Oy = 0.5f * (Zk.y + Zc.y);
        float2 w = g_wr[k];
        float re = Ex + w.x * Oy - w.y * Ox;
        float im = Ey - w.x * Ox - w.y * Oy;
        X[k] = __floats2bfloat162_rn(FWD_SCALE * re, FWD_SCALE * im);
    }
}

// ============== tensor-core block-diagonal complex 2-layer MLP ==============
// CTA = (mode-tile of 128, block n, batch b). 256 threads; 8 warps x 16 modes.
// Per-layer weight staging (36.9 KB at a time) -> 91.6 KB smem -> 2 CTAs/SM.
#define MT    128
#define MLP_THREADS 256
#define XPAD  104
#define RS    52                             // XPAD/2 words
#define SWL_BYTES (WFRAG_HALF * 2)           // 36864 B: one layer's fragments
#define SXR_OFF  SWL_BYTES
#define SXI_OFF  (SXR_OFF + MT * XPAD * 2)   // +26624
#define SB_OFF   (SXI_OFF + MT * XPAD * 2)   // +26624
#define MLP_SMEM (SB_OFF + 4 * 96 * 4)       // +1536 = 91648 B

__device__ __forceinline__ void mma_bf16(float* c, const uint32_t* a, uint32_t b0, uint32_t b1) {
    asm volatile(
        "mma.sync.aligned.m16n8k16.row.col.f32.bf16.bf16.f32 "
        "{%0,%1,%2,%3}, {%4,%5,%6,%7}, {%8,%9}, {%0,%1,%2,%3};"
        : "+f"(c[0]), "+f"(c[1]), "+f"(c[2]), "+f"(c[3])
        : "r"(a[0]), "r"(a[1]), "r"(a[2]), "r"(a[3]), "r"(b0), "r"(b1));
}

__global__ void __launch_bounds__(MLP_THREADS, 2) mlp_mma_kernel(const float* __restrict__ b1,
                                                                 const float* __restrict__ b2) {
    extern __shared__ char sm[];
    __nv_bfloat16* s_wf = (__nv_bfloat16*)sm;              // one layer, fragment order
    __nv_bfloat16* s_xr = (__nv_bfloat16*)(sm + SXR_OFF);  // [MT][XPAD]
    __nv_bfloat16* s_xi = (__nv_bfloat16*)(sm + SXI_OFF);
    float*         s_bv = (float*)(sm + SB_OFF);           // [4][96]

    const int tid = threadIdx.x;
    const int n   = blockIdx.y;
    const int b   = blockIdx.z;
    const int m0  = blockIdx.x * MT;

    const uint4* wsrc = (const uint4*)(g_wfrag + (size_t)n * WFRAG_N);
    uint4* wdst = (uint4*)s_wf;

    // ---- stage layer-1 weights ----
    #pragma unroll
    for (int i = tid; i < WFRAG_HALF / 8; i += MLP_THREADS)   // 2304 uint4
        wdst[i] = wsrc[i];
    if (tid < 96) {
        s_bv[tid]       = b1[n * 96 + tid];
        s_bv[96 + tid]  = b1[768 + n * 96 + tid];
        s_bv[192 + tid] = b2[n * 96 + tid];
        s_bv[288 + tid] = b2[768 + n * 96 + tid];
    }

    size_t rowbase = ((size_t)b * CH + n * 96) * (size_t)MODES;
    for (int i = tid; i < 96 * MT; i += MLP_THREADS) {
        int d = i >> 7, mm = i & (MT - 1);
        int mode = m0 + mm;
        __nv_bfloat162 xv = (mode < MODES) ? g_X[rowbase + (size_t)d * MODES + mode]
                                           : __nv_bfloat162{__float2bfloat16_rn(0.f), __float2bfloat16_rn(0.f)};
        s_xr[mm * XPAD + d] = xv.x;
        s_xi[mm * XPAD + d] = xv.y;
    }
    __syncthreads();

    const int lane = tid & 31;
    const int warp = tid >> 5;           // 0..7
    const int g  = lane >> 2;
    const int t  = lane & 3;
    const int mrow = warp * 16;          // each warp owns 16 modes (warp-private rows)

    const uint4*    Wf = (const uint4*)s_wf;
    const uint32_t* Xr = (const uint32_t*)s_xr;
    const uint32_t* Xi = (const uint32_t*)s_xi;
    const uint32_t SGN = 0x80008000u;

    float cr[12][4], ci[12][4];

    // ---------- layer 1 ----------
    #pragma unroll
    for (int nt = 0; nt < 12; nt++) {
        float br0 = s_bv[nt * 8 + 2 * t], br1 = s_bv[nt * 8 + 2 * t + 1];
        float bi0 = s_bv[96 + nt * 8 + 2 * t], bi1 = s_bv[96 + nt * 8 + 2 * t + 1];
        cr[nt][0] = br0; cr[nt][1] = br1; cr[nt][2] = br0; cr[nt][3] = br1;
        ci[nt][0] = bi0; ci[nt][1] = bi1; ci[nt][2] = bi0; ci[nt][3] = bi1;
    }
    #pragma unroll
    for (int k = 0; k < 6; k++) {
        int kw = k * 8 + t;
        uint32_t ar[4], ai[4], nai[4];
        int r0 = (mrow + g) * RS, r1 = (mrow + g + 8) * RS;
        ar[0] = Xr[r0 + kw];     ar[1] = Xr[r1 + kw];
        ar[2] = Xr[r0 + kw + 4]; ar[3] = Xr[r1 + kw + 4];
        ai[0] = Xi[r0 + kw];     ai[1] = Xi[r1 + kw];
        ai[2] = Xi[r0 + kw + 4]; ai[3] = Xi[r1 + kw + 4];
        #pragma unroll
        for (int j = 0; j < 4; j++) nai[j] = ai[j] ^ SGN;
        #pragma unroll
        for (int nt = 0; nt < 12; nt++) {
            uint4 wv = Wf[(k * 12 + nt) * 32 + lane];
            mma_bf16(cr[nt], ar,  wv.x, wv.y);
            mma_bf16(ci[nt], ai,  wv.x, wv.y);
            mma_bf16(cr[nt], nai, wv.z, wv.w);
            mma_bf16(ci[nt], ar,  wv.z, wv.w);
        }
    }
    __syncwarp();
    // relu -> bf16 -> back into x tile (warp-private rows)
    {
        uint32_t* Xrw = (uint32_t*)s_xr;
        uint32_t* Xiw = (uint32_t*)s_xi;
        #pragma unroll
        for (int nt = 0; nt < 12; nt++) {
            int cw = nt * 4 + t;
            int r0 = (mrow + g) * RS, r1 = (mrow + g + 8) * RS;
            __nv_bfloat162 hh;
            hh = __floats2bfloat162_rn(fmaxf(cr[nt][0], 0.0f), fmaxf(cr[nt][1], 0.0f));
            Xrw[r0 + cw] = *(uint32_t*)&hh;
            hh = __floats2bfloat162_rn(fmaxf(cr[nt][2], 0.0f), fmaxf(cr[nt][3], 0.0f));
            Xrw[r1 + cw] = *(uint32_t*)&hh;
            hh = __floats2bfloat162_rn(fmaxf(ci[nt][0], 0.0f), fmaxf(ci[nt][1], 0.0f));
            Xiw[r0 + cw] = *(uint32_t*)&hh;
            hh = __floats2bfloat162_rn(fmaxf(ci[nt][2], 0.0f), fmaxf(ci[nt][3], 0.0f));
            Xiw[r1 + cw] = *(uint32_t*)&hh;
        }
    }
    __syncthreads();   // all warps done with layer-1 weights buffer

    // ---- stage layer-2 weights over the same buffer ----
    #pragma unroll
    for (int i = tid; i < WFRAG_HALF / 8; i += MLP_THREADS)
        wdst[i] = wsrc[WFRAG_HALF / 8 + i];
    __syncthreads();

    // ---------- layer 2 ----------
    #pragma unroll
    for (int nt = 0; nt < 12; nt++) {
        float br0 = s_bv[192 + nt * 8 + 2 * t], br1 = s_bv[192 + nt * 8 + 2 * t + 1];
        float bi0 = s_bv[288 + nt * 8 + 2 * t], bi1 = s_bv[288 + nt * 8 + 2 * t + 1];
        cr[nt][0] = br0; cr[nt][1] = br1; cr[nt][2] = br0; cr[nt][3] = br1;
        ci[nt][0] = bi0; ci[nt][1] = bi1; ci[nt][2] = bi0; ci[nt][3] = bi1;
    }
    #pragma unroll
    for (int k = 0; k < 6; k++) {
        int kw = k * 8 + t;
        uint32_t ar[4], ai[4], nai[4];
        int r0 = (mrow + g) * RS, r1 = (mrow + g + 8) * RS;
        ar[0] = Xr[r0 + kw];     ar[1] = Xr[r1 + kw];
        ar[2] = Xr[r0 + kw + 4]; ar[3] = Xr[r1 + kw + 4];
        ai[0] = Xi[r0 + kw];     ai[1] = Xi[r1 + kw];
        ai[2] = Xi[r0 + kw + 4]; ai[3] = Xi[r1 + kw + 4];
        #pragma unroll
        for (int j = 0; j < 4; j++) nai[j] = ai[j] ^ SGN;
        #pragma unroll
        for (int nt = 0; nt < 12; nt++) {
            uint4 wv = Wf[(k * 12 + nt) * 32 + lane];
            mma_bf16(cr[nt], ar,  wv.x, wv.y);
            mma_bf16(ci[nt], ai,  wv.x, wv.y);
            mma_bf16(cr[nt], nai, wv.z, wv.w);
            mma_bf16(ci[nt], ar,  wv.z, wv.w);
        }
    }

    // ---------- softshrink + store (bf16x2) ----------
    int mode_lo = m0 + mrow + g;
    int mode_hi = mode_lo + 8;
    #pragma unroll
    for (int nt = 0; nt < 12; nt++) {
        #pragma unroll
        for (int j = 0; j < 4; j++) {
            int col  = nt * 8 + 2 * t + (j & 1);
            int mode = (j < 2) ? mode_lo : mode_hi;
            if (mode < MODES) {
                size_t off = rowbase + (size_t)col * MODES + mode;
                float vr = cr[nt][j];
                float vi = ci[nt][j];
                vr = copysignf(fmaxf(fabsf(vr) - LAM, 0.0f), vr);
                vi = copysignf(fmaxf(fabsf(vi) - LAM, 0.0f), vi);
                g_X[off] = __floats2bfloat162_rn(vr, vi);
            }
        }
    }
}

// ---------------- inverse rfft: X planar bf16x2 -> yT bf16 ------------------
__global__ void __launch_bounds__(256, 4) inv_fft_kernel() {
    extern __shared__ char smraw[];
    float2* A = (float2*)smraw;
    int row = blockIdx.x;
    int tid = threadIdx.x;
    const __nv_bfloat162* X = g_X + (size_t)row * MODES;

    float2 v[16];
    #pragma unroll
    for (int j = 0; j < 16; j++) {
        int k = tid + (j << 8);
        __nv_bfloat162 xk = X[k];
        __nv_bfloat162 xc = X[4096 - k];
        float xkr = __bfloat162float(xk.x), xki = __bfloat162float(xk.y);
        float xcr = __bfloat162float(xc.x), xci = __bfloat162float(xc.y);
        if (k == 0) { xki = 0.0f; xci = 0.0f; }
        float Ex = 0.5f * (xkr + xcr), Ey = 0.5f * (xki - xci);
        float Gx = 0.5f * (xkr - xcr), Gy = 0.5f * (xki + xci);
        float2 w = g_wr[k];
        float WOx = w.x * Gx - w.y * Gy;
        float WOy = w.x * Gy + w.y * Gx;
        v[j] = make_float2(INV_SCALE * (Ex - WOy), -INV_SCALE * (Ey + WOx));
    }
    dft16(v);
    #pragma unroll
    for (int j = 0; j < 16; j++) {
        float2 y = v[4 * (j & 3) + (j >> 2)];
        if (j > 0) y = cmul(g_wfft[j * tid], y);
        A[IX(16 * tid + j)] = y;
    }
    __syncthreads();
    fft4096_tail(A);

    __nv_bfloat162* out = (__nv_bfloat162*)(g_yT + (size_t)row * SEQ);
    for (int j = tid; j < 4096; j += 256) {
        float2 r = A[IX(j)];
        out[j] = __floats2bfloat162_rn(r.x, -r.y);
    }
}

// ---------------- transpose + bias: out[b,s,c] = x[b,s,c] + yT[b,c,s] -------
__global__ void __launch_bounds__(256) final_kernel(const float* __restrict__ x,
                                                    float* __restrict__ out) {
    __shared__ float t[32][33];
    int b  = blockIdx.z;
    int c0 = blockIdx.x * 32;
    int s0 = blockIdx.y * 32;
    int tx = threadIdx.x, ty = threadIdx.y;
    #pragma unroll
    for (int i = 0; i < 4; i++) {
        int cc = c0 + ty + 8 * i;
        t[ty + 8 * i][tx] = __bfloat162float(g_yT[((size_t)b * CH + cc) * SEQ + s0 + tx]);
    }
    __syncthreads();
    #pragma unroll
    for (int i = 0; i < 4; i++) {
        int s = s0 + ty + 8 * i;
        size_t off = ((size_t)b * SEQ + s) * CH + c0 + tx;
        out[off] = x[off] + t[tx][ty + 8 * i];
    }
}

// ---------------- launcher ----------------
extern "C" void kernel_launch(void* const* d_in, const int* in_sizes, int n_in,
                              void* d_out, int out_size) {
    const float* x  = (const float*)d_in[0];
    const float* w1 = (const float*)d_in[1];
    const float* b1 = (const float*)d_in[2];
    const float* w2 = (const float*)d_in[3];
    const float* b2 = (const float*)d_in[4];
    float* out = (float*)d_out;

    cudaFuncSetAttribute(fwd_fft_kernel, cudaFuncAttributeMaxDynamicSharedMemorySize, FFT_SMEM);
    cudaFuncSetAttribute(inv_fft_kernel, cudaFuncAttributeMaxDynamicSharedMemorySize, FFT_SMEM);
    cudaFuncSetAttribute(mlp_mma_kernel, cudaFuncAttributeMaxDynamicSharedMemorySize, MLP_SMEM);

    init_tables_kernel<<<17, 256>>>();
    pack_w_kernel<<<NBLK, 512>>>(w1, w2);
    transpose_x_kernel<<<dim3(CH / 32, SEQ / 64, BATCH), dim3(32, 8)>>>(x);
    fwd_fft_kernel<<<BATCH * CH, 256, FFT_SMEM>>>();
    mlp_mma_kernel<<<dim3((MODES + MT - 1) / MT, NBLK, BATCH), MLP_THREADS, MLP_SMEM>>>(b1, b2);
    inv_fft_kernel<<<BATCH * CH, 256, FFT_SMEM>>>();
    final_kernel<<<dim3(CH / 32, SEQ / 32, BATCH), dim3(32, 8)>>>(x, out);
}

// round 17
// speedup vs baseline: 1.1275x; 1.0361x over previous
#include <cuda_runtime.h>
#include <cuda_bf16.h>
#include <math.h>
#include <stdint.h>

#define BATCH 4
#define SEQ   8192
#define CH    768
#define N2    4096
#define MODES 4097
#define NBLK  8
#define LAM   0.01f

#define FWD_SCALE 0.011048543456039806f   // 1/sqrt(8192)
#define INV_SCALE 0.022097086912079613f   // sqrt(8192)/4096

// padded smem indexing: 1 extra float2 per 32 -> kills 128B-stride conflicts
#define IX(i) ((i) + ((i) >> 5))
#define FFT_BUF 4224
#define FFT_SMEM (FFT_BUF * 8)            // 33792 bytes (single in-place buffer)

#define WFRAG_HALF 18432                  // bf16 elems per layer: 6*12*32*8
#define WFRAG_N    (2 * WFRAG_HALF)       // per block n

// ---------------- device scratch ----------------
__device__ __nv_bfloat16  g_xTb[BATCH * CH * SEQ];       // x transposed [b][c][s], bf16
__device__ __nv_bfloat162 g_X [BATCH * CH * MODES];      // spectrum (re,im) bf16x2
__device__ __nv_bfloat16  g_yT[BATCH * CH * SEQ];        // irfft out [b][c][s]
__device__ __nv_bfloat16  g_wfrag[NBLK * WFRAG_N];       // fragment-packed weights
__device__ float2 g_wfft[N2];     // exp(-2*pi*i*t/4096)
__device__ float2 g_wr  [MODES];  // (cos,sin)(2*pi*k/8192)

// ---------------- tables ----------------
__global__ void init_tables_kernel() {
    int i = blockIdx.x * blockDim.x + threadIdx.x;
    if (i < N2) {
        float s, c;
        sincospif((float)i * (1.0f / 2048.0f), &s, &c);
        g_wfft[i] = make_float2(c, -s);
    }
    if (i < MODES) {
        float s, c;
        sincospif((float)i * (1.0f / 4096.0f), &s, &c);
        g_wr[i] = make_float2(c, s);
    }
}

// ---------------- one-shot weight fragment packing ----------------
__global__ void __launch_bounds__(512) pack_w_kernel(const float* __restrict__ w1,
                                                     const float* __restrict__ w2) {
    int n = blockIdx.x;
    const float* g_w1r = w1 + n * 9216;
    const float* g_w1i = w1 + 73728 + n * 9216;
    const float* g_w2r = w2 + n * 9216;
    const float* g_w2i = w2 + 73728 + n * 9216;
    __nv_bfloat16* dst = g_wfrag + n * WFRAG_N;
    for (int i = threadIdx.x; i < 9216; i += 512) {
        int d = i / 96, kout = i % 96;
        int k  = d >> 4;
        int r  = d & 15;
        int half = r >> 3;
        int t2   = (r & 7) >> 1;
        int e    = r & 1;
        int nt = kout >> 3, gg = kout & 7;
        int base = (((k * 12 + nt) * 32 + gg * 4 + t2) << 3) + half * 2 + e;
        dst[base]                  = __float2bfloat16_rn(g_w1r[i]);
        dst[base + 4]              = __float2bfloat16_rn(g_w1i[i]);
        dst[WFRAG_HALF + base]     = __float2bfloat16_rn(g_w2r[i]);
        dst[WFRAG_HALF + base + 4] = __float2bfloat16_rn(g_w2i[i]);
    }
}

// -------- transpose x: [b,s,c] fp32 -> xTb [b,c,s] bf16 (paired stores) -----
__global__ void __launch_bounds__(256) transpose_x_kernel(const float* __restrict__ x) {
    __shared__ float t[64][33];
    int b  = blockIdx.z;
    int c0 = blockIdx.x * 32;
    int s0 = blockIdx.y * 64;
    int tx = threadIdx.x, ty = threadIdx.y;
    #pragma unroll
    for (int i = 0; i < 8; i++) {
        int s = s0 + ty + 8 * i;
        t[ty + 8 * i][tx] = x[((size_t)b * SEQ + s) * CH + c0 + tx];
    }
    __syncthreads();
    #pragma unroll
    for (int i = 0; i < 4; i++) {
        int cc = c0 + ty + 8 * i;
        __nv_bfloat162 v = __floats2bfloat162_rn(t[2 * tx][cc - c0], t[2 * tx + 1][cc - c0]);
        *(__nv_bfloat162*)(g_xTb + ((size_t)b * CH + cc) * SEQ + s0 + 2 * tx) = v;
    }
}

// ---------------- complex helpers ----------------
__device__ __forceinline__ float2 cadd(float2 a, float2 b) { return make_float2(a.x + b.x, a.y + b.y); }
__device__ __forceinline__ float2 csub(float2 a, float2 b) { return make_float2(a.x - b.x, a.y - b.y); }
__device__ __forceinline__ float2 cmul(float2 a, float2 b) {
    return make_float2(fmaf(a.x, b.x, -a.y * b.y), fmaf(a.x, b.y, a.y * b.x));
}

// forward DFT4 (e^{-i}), in place
__device__ __forceinline__ void dft4(float2& a0, float2& a1, float2& a2, float2& a3) {
    float2 t0 = cadd(a0, a2), t1 = csub(a0, a2);
    float2 t2 = cadd(a1, a3), t3 = csub(a1, a3);
    a0 = cadd(t0, t2);
    a2 = csub(t0, t2);
    a1 = make_float2(t1.x + t3.y, t1.y - t3.x);
    a3 = make_float2(t1.x - t3.y, t1.y + t3.x);
}

// 16-pt DFT in registers; output X[j] lands in v[4*(j&3) + (j>>2)]
__device__ __forceinline__ void dft16(float2 v[16]) {
    #pragma unroll
    for (int i = 0; i < 4; i++) dft4(v[i], v[i + 4], v[i + 8], v[i + 12]);
    const float C1 = 0.92387953251128674f, S1 = 0.38268343236508978f, R = 0.70710678118654752f;
    v[5]  = cmul(make_float2( C1, -S1), v[5]);
    v[6]  = cmul(make_float2(  R,  -R), v[6]);
    v[7]  = cmul(make_float2( S1, -C1), v[7]);
    v[9]  = cmul(make_float2(  R,  -R), v[9]);
    v[10] = make_float2(v[10].y, -v[10].x);
    v[11] = cmul(make_float2( -R,  -R), v[11]);
    v[13] = cmul(make_float2( S1, -C1), v[13]);
    v[14] = cmul(make_float2( -R,  -R), v[14]);
    v[15] = cmul(make_float2(-C1,  S1), v[15]);
    #pragma unroll
    for (int k1 = 0; k1 < 4; k1++) dft4(v[4 * k1], v[4 * k1 + 1], v[4 * k1 + 2], v[4 * k1 + 3]);
}

// Stages 1 and 2 of the 4096-pt radix-16 Stockham (stage 0 fused by callers).
__device__ __forceinline__ void fft4096_tail(float2* A) {
    int tid = threadIdx.x;
    float2 v[16];
    // ---- stage 1: ls=4, m=16 ----
    {
        int q = tid & 15, p = tid >> 4;
        #pragma unroll
        for (int j = 0; j < 16; j++)
            v[j] = A[IX(q + ((p + (j << 4)) << 4))];
        __syncthreads();
        dft16(v);
        int twb = p << 4;
        #pragma unroll
        for (int j = 0; j < 16; j++) {
            float2 y = v[4 * (j & 3) + (j >> 2)];
            if (j > 0) y = cmul(g_wfft[j * twb], y);
            A[IX(q + ((16 * p + j) << 4))] = y;
        }
        __syncthreads();
    }
    // ---- stage 2: ls=8, p=0 -> twiddle-free, per-thread disjoint ----
    {
        #pragma unroll
        for (int j = 0; j < 16; j++)
            v[j] = A[IX(tid + (j << 8))];
        dft16(v);
        #pragma unroll
        for (int j = 0; j < 16; j++)
            A[IX(tid + (j << 8))] = v[4 * (j & 3) + (j >> 2)];
        __syncthreads();
    }
}

// ---------------- forward rfft: xTb bf16 -> X planar bf16x2 -----------------
// Epilogue pairs modes k and 4096-k (same Z pair) -> half the smem/table reads.
__global__ void __launch_bounds__(256, 4) fwd_fft_kernel() {
    extern __shared__ char smraw[];
    float2* A = (float2*)smraw;
    int row = blockIdx.x;
    int tid = threadIdx.x;
    const __nv_bfloat162* xr = (const __nv_bfloat162*)(g_xTb + (size_t)row * SEQ);

    float2 v[16];
    #pragma unroll
    for (int j = 0; j < 16; j++) {
        __nv_bfloat162 p = xr[tid + (j << 8)];
        v[j] = make_float2(__bfloat162float(p.x), __bfloat162float(p.y));
    }
    dft16(v);
    #pragma unroll
    for (int j = 0; j < 16; j++) {
        float2 y = v[4 * (j & 3) + (j >> 2)];
        if (j > 0) y = cmul(g_wfft[j * tid], y);
        A[IX(16 * tid + j)] = y;
    }
    __syncthreads();
    fft4096_tail(A);

    __nv_bfloat162* X = g_X + (size_t)row * MODES;
    for (int k = tid; k <= 2048; k += 256) {
        float2 Zk = A[IX(k)];
        float2 Zc = A[IX((4096 - k) & 4095)];
        float Ex = 0.5f * (Zk.x + Zc.x), Ey = 0.5f * (Zk.y - Zc.y);
        float Ox = 0.5f * (Zk.x - Zc.x), Oy = 0.5f * (Zk.y + Zc.y);
        float2 w = g_wr[k];
        float re = Ex + w.x * Oy - w.y * Ox;
        float im = Ey - w.x * Ox - w.y * Oy;
        X[k] = __floats2bfloat162_rn(FWD_SCALE * re, FWD_SCALE * im);
        if (k != 2048) {
            // mode 4096-k from the same pair: w' = (-w.x, w.y), E'=(Ex,-Ey), O'=(-Ox,Oy)
            float re2 = Ex - w.x * Oy + w.y * Ox;
            float im2 = -Ey - w.x * Ox - w.y * Oy;
            X[4096 - k] = __floats2bfloat162_rn(FWD_SCALE * re2, FWD_SCALE * im2);
        }
    }
}

// ============== tensor-core block-diagonal complex 2-layer MLP ==============
// CTA = (mode-tile of 128, block n, batch b). 256 threads; 8 warps x 16 modes.
// wA (full layer, 36.9KB) + wB (rotating half, 18.4KB); layer-2 weights stream
// in via cp.async behind layer-1 / layer-2 compute. 110KB smem -> 2 CTAs/SM.
#define MT    128
#define MLP_THREADS 256
#define XPAD  104
#define RS    52                             // XPAD/2 words
#define SWA_OFF  0                           // 36864 B
#define SWB_OFF  36864                       // 18432 B
#define SXR_OFF  55296
#define SXI_OFF  (SXR_OFF + MT * XPAD * 2)   // +26624 = 81920
#define SB_OFF   (SXI_OFF + MT * XPAD * 2)   // +26624 = 108544
#define MLP_SMEM (SB_OFF + 4 * 96 * 4)       // +1536 = 110080 B

__device__ __forceinline__ void mma_bf16(float* c, const uint32_t* a, uint32_t b0, uint32_t b1) {
    asm volatile(
        "mma.sync.aligned.m16n8k16.row.col.f32.bf16.bf16.f32 "
        "{%0,%1,%2,%3}, {%4,%5,%6,%7}, {%8,%9}, {%0,%1,%2,%3};"
        : "+f"(c[0]), "+f"(c[1]), "+f"(c[2]), "+f"(c[3])
        : "r"(a[0]), "r"(a[1]), "r"(a[2]), "r"(a[3]), "r"(b0), "r"(b1));
}

__device__ __forceinline__ void cp16(void* smem, const void* gmem) {
    uint32_t sa = (uint32_t)__cvta_generic_to_shared(smem);
    asm volatile("cp.async.cg.shared.global [%0], [%1], 16;" :: "r"(sa), "l"(gmem));
}

__global__ void __launch_bounds__(MLP_THREADS, 2) mlp_mma_kernel(const float* __restrict__ b1,
                                                                 const float* __restrict__ b2) {
    extern __shared__ char sm[];
    uint4* wA = (uint4*)(sm + SWA_OFF);                    // full layer fragments
    uint4* wB = (uint4*)(sm + SWB_OFF);                    // half layer fragments
    __nv_bfloat16* s_xr = (__nv_bfloat16*)(sm + SXR_OFF);  // [MT][XPAD]
    __nv_bfloat16* s_xi = (__nv_bfloat16*)(sm + SXI_OFF);
    float*         s_bv = (float*)(sm + SB_OFF);           // [4][96]

    const int tid = threadIdx.x;
    const int n   = blockIdx.y;
    const int b   = blockIdx.z;
    const int m0  = blockIdx.x * MT;

    const uint4* wsrc = (const uint4*)(g_wfrag + (size_t)n * WFRAG_N);  // 4608 uint4

    // ---- async: layer-2 first half (k=0..2) -> wB (overlaps w1 sync copy) ----
    for (int i = tid; i < 1152; i += MLP_THREADS)
        cp16(wB + i, wsrc + 2304 + i);
    asm volatile("cp.async.commit_group;" ::: "memory");

    // ---- sync: layer-1 weights -> wA ----
    #pragma unroll
    for (int i = tid; i < 2304; i += MLP_THREADS)
        wA[i] = wsrc[i];
    if (tid < 96) {
        s_bv[tid]       = b1[n * 96 + tid];
        s_bv[96 + tid]  = b1[768 + n * 96 + tid];
        s_bv[192 + tid] = b2[n * 96 + tid];
        s_bv[288 + tid] = b2[768 + n * 96 + tid];
    }

    size_t rowbase = ((size_t)b * CH + n * 96) * (size_t)MODES;
    for (int i = tid; i < 96 * MT; i += MLP_THREADS) {
        int d = i >> 7, mm = i & (MT - 1);
        int mode = m0 + mm;
        __nv_bfloat162 xv = (mode < MODES) ? g_X[rowbase + (size_t)d * MODES + mode]
                                           : __nv_bfloat162{__float2bfloat16_rn(0.f), __float2bfloat16_rn(0.f)};
        s_xr[mm * XPAD + d] = xv.x;
        s_xi[mm * XPAD + d] = xv.y;
    }
    __syncthreads();

    const int lane = tid & 31;
    const int warp = tid >> 5;           // 0..7
    const int g  = lane >> 2;
    const int t  = lane & 3;
    const int mrow = warp * 16;          // each warp owns 16 modes

    const uint32_t* Xr = (const uint32_t*)s_xr;
    const uint32_t* Xi = (const uint32_t*)s_xi;
    const uint32_t SGN = 0x80008000u;

    float cr[12][4], ci[12][4];

    // ---------- layer 1 (weights in wA) ----------
    #pragma unroll
    for (int nt = 0; nt < 12; nt++) {
        float br0 = s_bv[nt * 8 + 2 * t], br1 = s_bv[nt * 8 + 2 * t + 1];
        float bi0 = s_bv[96 + nt * 8 + 2 * t], bi1 = s_bv[96 + nt * 8 + 2 * t + 1];
        cr[nt][0] = br0; cr[nt][1] = br1; cr[nt][2] = br0; cr[nt][3] = br1;
        ci[nt][0] = bi0; ci[nt][1] = bi1; ci[nt][2] = bi0; ci[nt][3] = bi1;
    }
    #pragma unroll
    for (int k = 0; k < 6; k++) {
        int kw = k * 8 + t;
        uint32_t ar[4], ai[4], nai[4];
        int r0 = (mrow + g) * RS, r1 = (mrow + g + 8) * RS;
        ar[0] = Xr[r0 + kw];     ar[1] = Xr[r1 + kw];
        ar[2] = Xr[r0 + kw + 4]; ar[3] = Xr[r1 + kw + 4];
        ai[0] = Xi[r0 + kw];     ai[1] = Xi[r1 + kw];
        ai[2] = Xi[r0 + kw + 4]; ai[3] = Xi[r1 + kw + 4];
        #pragma unroll
        for (int j = 0; j < 4; j++) nai[j] = ai[j] ^ SGN;
        #pragma unroll
        for (int nt = 0; nt < 12; nt++) {
            uint4 wv = wA[(k * 12 + nt) * 32 + lane];
            mma_bf16(cr[nt], ar,  wv.x, wv.y);
            mma_bf16(ci[nt], ai,  wv.x, wv.y);
            mma_bf16(cr[nt], nai, wv.z, wv.w);
            mma_bf16(ci[nt], ar,  wv.z, wv.w);
        }
    }
    __syncwarp();
    // relu -> bf16 -> back into x tile (warp-private rows)
    {
        uint32_t* Xrw = (uint32_t*)s_xr;
        uint32_t* Xiw = (uint32_t*)s_xi;
        #pragma unroll
        for (int nt = 0; nt < 12; nt++) {
            int cw = nt * 4 + t;
            int r0 = (mrow + g) * RS, r1 = (mrow + g + 8) * RS;
            __nv_bfloat162 hh;
            hh = __floats2bfloat162_rn(fmaxf(cr[nt][0], 0.0f), fmaxf(cr[nt][1], 0.0f));
            Xrw[r0 + cw] = *(uint32_t*)&hh;
            hh = __floats2bfloat162_rn(fmaxf(cr[nt][2], 0.0f), fmaxf(cr[nt][3], 0.0f));
            Xrw[r1 + cw] = *(uint32_t*)&hh;
            hh = __floats2bfloat162_rn(fmaxf(ci[nt][0], 0.0f), fmaxf(ci[nt][1], 0.0f));
            Xiw[r0 + cw] = *(uint32_t*)&hh;
            hh = __floats2bfloat162_rn(fmaxf(ci[nt][2], 0.0f), fmaxf(ci[nt][3], 0.0f));
            Xiw[r1 + cw] = *(uint32_t*)&hh;
        }
    }
    __syncthreads();   // all warps done with wA + x tile rewritten

    // ---- async: layer-2 second half (k=3..5) -> wA (now dead) ----
    for (int i = tid; i < 1152; i += MLP_THREADS)
        cp16(wA + i, wsrc + 3456 + i);
    asm volatile("cp.async.commit_group;" ::: "memory");
    asm volatile("cp.async.wait_group 1;" ::: "memory");   // wB ready
    __syncthreads();

    // ---------- layer 2 ----------
    #pragma unroll
    for (int nt = 0; nt < 12; nt++) {
        float br0 = s_bv[192 + nt * 8 + 2 * t], br1 = s_bv[192 + nt * 8 + 2 * t + 1];
        float bi0 = s_bv[288 + nt * 8 + 2 * t], bi1 = s_bv[288 + nt * 8 + 2 * t + 1];
        cr[nt][0] = br0; cr[nt][1] = br1; cr[nt][2] = br0; cr[nt][3] = br1;
        ci[nt][0] = bi0; ci[nt][1] = bi1; ci[nt][2] = bi0; ci[nt][3] = bi1;
    }
    // part 1: k = 0..2 from wB
    #pragma unroll
    for (int k = 0; k < 3; k++) {
        int kw = k * 8 + t;
        uint32_t ar[4], ai[4], nai[4];
        int r0 = (mrow + g) * RS, r1 = (mrow + g + 8) * RS;
        ar[0] = Xr[r0 + kw];     ar[1] = Xr[r1 + kw];
        ar[2] = Xr[r0 + kw + 4]; ar[3] = Xr[r1 + kw + 4];
        ai[0] = Xi[r0 + kw];     ai[1] = Xi[r1 + kw];
        ai[2] = Xi[r0 + kw + 4]; ai[3] = Xi[r1 + kw + 4];
        #pragma unroll
        for (int j = 0; j < 4; j++) nai[j] = ai[j] ^ SGN;
        #pragma unroll
        for (int nt = 0; nt < 12; nt++) {
            uint4 wv = wB[(k * 12 + nt) * 32 + lane];
            mma_bf16(cr[nt], ar,  wv.x, wv.y);
            mma_bf16(ci[nt], ai,  wv.x, wv.y);
            mma_bf16(cr[nt], nai, wv.z, wv.w);
            mma_bf16(ci[nt], ar,  wv.z, wv.w);
        }
    }
    asm volatile("cp.async.wait_group 0;" ::: "memory");   // wA half ready
    __syncthreads();
    // part 2: k = 3..5 from wA (stored at local k-3)
    #pragma unroll
    for (int k = 3; k < 6; k++) {
        int kw = k * 8 + t;
        uint32_t ar[4], ai[4], nai[4];
        int r0 = (mrow + g) * RS, r1 = (mrow + g + 8) * RS;
        ar[0] = Xr[r0 + kw];     ar[1] = Xr[r1 + kw];
        ar[2] = Xr[r0 + kw + 4]; ar[3] = Xr[r1 + kw + 4];
        ai[0] = Xi[r0 + kw];     ai[1] = Xi[r1 + kw];
        ai[2] = Xi[r0 + kw + 4]; ai[3] = Xi[r1 + kw + 4];
        #pragma unroll
        for (int j = 0; j < 4; j++) nai[j] = ai[j] ^ SGN;
        #pragma unroll
        for (int nt = 0; nt < 12; nt++) {
            uint4 wv = wA[((k - 3) * 12 + nt) * 32 + lane];
            mma_bf16(cr[nt], ar,  wv.x, wv.y);
            mma_bf16(ci[nt], ai,  wv.x, wv.y);
            mma_bf16(cr[nt], nai, wv.z, wv.w);
            mma_bf16(ci[nt], ar,  wv.z, wv.w);
        }
    }

    // ---------- softshrink + store (bf16x2) ----------
    int mode_lo = m0 + mrow + g;
    int mode_hi = mode_lo + 8;
    #pragma unroll
    for (int nt = 0; nt < 12; nt++) {
        #pragma unroll
        for (int j = 0; j < 4; j++) {
            int col  = nt * 8 + 2 * t + (j & 1);
            int mode = (j < 2) ? mode_lo : mode_hi;
            if (mode < MODES) {
                size_t off = rowbase + (size_t)col * MODES + mode;
                float vr = cr[nt][j];
                float vi = ci[nt][j];
                vr = copysignf(fmaxf(fabsf(vr) - LAM, 0.0f), vr);
                vi = copysignf(fmaxf(fabsf(vi) - LAM, 0.0f), vi);
                g_X[off] = __floats2bfloat162_rn(vr, vi);
            }
        }
    }
}

// ---------------- inverse rfft: X planar bf16x2 -> yT bf16 ------------------
__global__ void __launch_bounds__(256, 4) inv_fft_kernel() {
    extern __shared__ char smraw[];
    float2* A = (float2*)smraw;
    int row = blockIdx.x;
    int tid = threadIdx.x;
    const __nv_bfloat162* X = g_X + (size_t)row * MODES;

    float2 v[16];
    #pragma unroll
    for (int j = 0; j < 16; j++) {
        int k = tid + (j << 8);
        __nv_bfloat162 xk = X[k];
        __nv_bfloat162 xc = X[4096 - k];
        float xkr = __bfloat162float(xk.x), xki = __bfloat162float(xk.y);
        float xcr = __bfloat162float(xc.x), xci = __bfloat162float(xc.y);
        if (k == 0) { xki = 0.0f; xci = 0.0f; }
        float Ex = 0.5f * (xkr + xcr), Ey = 0.5f * (xki - xci);
        float Gx = 0.5f * (xkr - xcr), Gy = 0.5f * (xki + xci);
        float2 w = g_wr[k];
        float WOx = w.x * Gx - w.y * Gy;
        float WOy = w.x * Gy + w.y * Gx;
        v[j] = make_float2(INV_SCALE * (Ex - WOy), -INV_SCALE * (Ey + WOx));
    }
    dft16(v);
    #pragma unroll
    for (int j = 0; j < 16; j++) {
        float2 y = v[4 * (j & 3) + (j >> 2)];
        if (j > 0) y = cmul(g_wfft[j * tid], y);
        A[IX(16 * tid + j)] = y;
    }
    __syncthreads();
    fft4096_tail(A);

    __nv_bfloat162* out = (__nv_bfloat162*)(g_yT + (size_t)row * SEQ);
    for (int j = tid; j < 4096; j += 256) {
        float2 r = A[IX(j)];
        out[j] = __floats2bfloat162_rn(r.x, -r.y);
    }
}

// ---------------- transpose + bias: out[b,s,c] = x[b,s,c] + yT[b,c,s] -------
__global__ void __launch_bounds__(256) final_kernel(const float* __restrict__ x,
                                                    float* __restrict__ out) {
    __shared__ float t[32][33];
    int b  = blockIdx.z;
    int c0 = blockIdx.x * 32;
    int s0 = blockIdx.y * 32;
    int tx = threadIdx.x, ty = threadIdx.y;
    #pragma unroll
    for (int i = 0; i < 4; i++) {
        int cc = c0 + ty + 8 * i;
        t[ty + 8 * i][tx] = __bfloat162float(g_yT[((size_t)b * CH + cc) * SEQ + s0 + tx]);
    }
    __syncthreads();
    #pragma unroll
    for (int i = 0; i < 4; i++) {
        int s = s0 + ty + 8 * i;
        size_t off = ((size_t)b * SEQ + s) * CH + c0 + tx;
        out[off] = x[off] + t[tx][ty + 8 * i];
    }
}

// ---------------- launcher ----------------
extern "C" void kernel_launch(void* const* d_in, const int* in_sizes, int n_in,
                              void* d_out, int out_size) {
    const float* x  = (const float*)d_in[0];
    const float* w1 = (const float*)d_in[1];
    const float* b1 = (const float*)d_in[2];
    const float* w2 = (const float*)d_in[3];
    const float* b2 = (const float*)d_in[4];
    float* out = (float*)d_out;

    cudaFuncSetAttribute(fwd_fft_kernel, cudaFuncAttributeMaxDynamicSharedMemorySize, FFT_SMEM);
    cudaFuncSetAttribute(inv_fft_kernel, cudaFuncAttributeMaxDynamicSharedMemorySize, FFT_SMEM);
    cudaFuncSetAttribute(mlp_mma_kernel, cudaFuncAttributeMaxDynamicSharedMemorySize, MLP_SMEM);

    init_tables_kernel<<<17, 256>>>();
    pack_w_kernel<<<NBLK, 512>>>(w1, w2);
    transpose_x_kernel<<<dim3(CH / 32, SEQ / 64, BATCH), dim3(32, 8)>>>(x);
    fwd_fft_kernel<<<BATCH * CH, 256, FFT_SMEM>>>();
    mlp_mma_kernel<<<dim3((MODES + MT - 1) / MT, NBLK, BATCH), MLP_THREADS, MLP_SMEM>>>(b1, b2);
    inv_fft_kernel<<<BATCH * CH, 256, FFT_SMEM>>>();
    final_kernel<<<dim3(CH / 32, SEQ / 32, BATCH), dim3(32, 8)>>>(x, out);
}